// round 15
// baseline (speedup 1.0000x reference)
#include <cuda_runtime.h>
#include <cuda_bf16.h>
#include <stdint.h>

#define NB 16
#define NN 1024
#define DD 64
#define OUT_OFF ((size_t)NB * NN * NN)

// ---------------- scratch (device globals; no allocation) ----------------
__device__ float g_rowmean[NB*NN];
__device__ float g_diag[NB*NN];
__device__ float g_r[NB*NN];            // c3*rowmean + c4*diag + p1
__device__ float g_s[NB];               // c1*mean_all + c2*mean_diag + p2
__device__ float g_meanX[NB*DD];
__device__ float g_T2[(size_t)NB*NN*DD];        // raw X@W2^T
__device__ uint32_t g_Bhi[(size_t)NB*DD*NN/2];  // bf16x2-packed hi of X2_t^T [b][e][k/2]
__device__ uint32_t g_Blo[(size_t)NB*DD*NN/2];  // bf16x2-packed lo residual
__device__ float g_part0[(size_t)NB*NN*DD];     // split-K partial (kv=0)
__device__ float g_part1[(size_t)NB*NN*DD];     // split-K partial (kv=1)
__device__ int   g_cnt[NB*8];                    // fold counters (zeroed by k_front)

// ---------------- packed fp32x2 helpers ----------------
__device__ __forceinline__ void fma2(unsigned long long &d,
                                     unsigned long long a,
                                     unsigned long long b) {
    asm("fma.rn.f32x2 %0, %1, %2, %0;" : "+l"(d) : "l"(a), "l"(b));
}
__device__ __forceinline__ float psum(unsigned long long v) {
    return __uint_as_float((unsigned)v) + __uint_as_float((unsigned)(v >> 32));
}

// ---------------- bf16 split helpers ----------------
__device__ __forceinline__ uint32_t prmt7632(uint32_t a, uint32_t b) {
    uint32_t d;
    asm("prmt.b32 %0, %1, %2, 0x7632;" : "=r"(d) : "r"(a), "r"(b));
    return d;
}

// ---------------- m16n8k16 bf16 mma (HMMA, baseline PTX) ----------------
__device__ __forceinline__ void mma16(float* c, const uint32_t* a,
                                      uint32_t b0, uint32_t b1) {
    asm("mma.sync.aligned.m16n8k16.row.col.f32.bf16.bf16.f32 "
        "{%0,%1,%2,%3}, {%4,%5,%6,%7}, {%8,%9}, {%0,%1,%2,%3};"
        : "+f"(c[0]), "+f"(c[1]), "+f"(c[2]), "+f"(c[3])
        : "r"(a[0]), "r"(a[1]), "r"(a[2]), "r"(a[3]), "r"(b0), "r"(b1));
}

// ============ kernel 1 (fused front) ============
// blocks 0-255   : X@W GEMMs, 64-row tiles (small, 2/SM, hidden under A read)
// blocks 256-271 : meanX + counter zero
// blocks 272-2319: per-row stats (reads all of A -> DRAM-bound critical path)
__global__ __launch_bounds__(256) void k_front(
    const float* __restrict__ A, const float* __restrict__ X,
    const float* __restrict__ coeffs, const float* __restrict__ wA1,
    const float* __restrict__ w11, const float* __restrict__ w21,
    float* __restrict__ x1o)
{
    const int bid = blockIdx.x;
    const int tid = threadIdx.x;

    if (bid < 256) {
        // ---- X@W1^T -> x1o (raw), X@W2^T -> g_T2 (raw); 64-row tile ----
        extern __shared__ __align__(16) float sm[];
        float* Xs = sm;               // [64][64]
        float* W1 = sm + 64*DD;       // [64][68]
        float* W2 = W1 + 64*68;       // [64][68]

        const int b = bid >> 4;
        const int it0 = (bid & 15) << 6;
        const int c4 = tid & 15, r0 = tid >> 4;
        const int ci = c4 << 2;

        const float* Xb = X + ((size_t)b*NN + it0)*DD;
#pragma unroll
        for (int t = 0; t < 4; ++t) {
            int row = r0 + (t << 4);
            *reinterpret_cast<float4*>(Xs + row*DD + ci) =
                *reinterpret_cast<const float4*>(Xb + (size_t)row*DD + ci);
        }
#pragma unroll
        for (int t = 0; t < 4; ++t) {
            int e = r0 + (t << 4);
            *reinterpret_cast<float4*>(W1 + e*68 + ci) = *reinterpret_cast<const float4*>(w11 + e*DD + ci);
            *reinterpret_cast<float4*>(W2 + e*68 + ci) = *reinterpret_cast<const float4*>(w21 + e*DD + ci);
        }
        __syncthreads();

        const int tx = tid & 15, ty = tid >> 4;
        const int e0 = tx << 2, i0 = ty << 2;   // 4 rows x 4 e per thread

        unsigned long long acc[4][4];
        // pass 1: X@W1^T
#pragma unroll
        for (int r = 0; r < 4; ++r)
#pragma unroll
            for (int q = 0; q < 4; ++q) acc[r][q] = 0ull;
#pragma unroll 2
        for (int d = 0; d < DD; d += 4) {
            ulonglong2 a[4];
#pragma unroll
            for (int r = 0; r < 4; ++r)
                a[r] = *reinterpret_cast<const ulonglong2*>(Xs + (i0+r)*DD + d);
#pragma unroll
            for (int q = 0; q < 4; ++q) {
                ulonglong2 bv = *reinterpret_cast<const ulonglong2*>(W1 + (e0+q)*68 + d);
#pragma unroll
                for (int r = 0; r < 4; ++r) { fma2(acc[r][q], a[r].x, bv.x); fma2(acc[r][q], a[r].y, bv.y); }
            }
        }
#pragma unroll
        for (int r = 0; r < 4; ++r) {
            float4 o;
            o.x = psum(acc[r][0]); o.y = psum(acc[r][1]);
            o.z = psum(acc[r][2]); o.w = psum(acc[r][3]);
            *reinterpret_cast<float4*>(x1o + ((size_t)b*NN + it0 + i0 + r)*DD + e0) = o;
        }
        // pass 2: X@W2^T
#pragma unroll
        for (int r = 0; r < 4; ++r)
#pragma unroll
            for (int q = 0; q < 4; ++q) acc[r][q] = 0ull;
#pragma unroll 2
        for (int d = 0; d < DD; d += 4) {
            ulonglong2 a[4];
#pragma unroll
            for (int r = 0; r < 4; ++r)
                a[r] = *reinterpret_cast<const ulonglong2*>(Xs + (i0+r)*DD + d);
#pragma unroll
            for (int q = 0; q < 4; ++q) {
                ulonglong2 bv = *reinterpret_cast<const ulonglong2*>(W2 + (e0+q)*68 + d);
#pragma unroll
                for (int r = 0; r < 4; ++r) { fma2(acc[r][q], a[r].x, bv.x); fma2(acc[r][q], a[r].y, bv.y); }
            }
        }
#pragma unroll
        for (int r = 0; r < 4; ++r) {
            float4 o;
            o.x = psum(acc[r][0]); o.y = psum(acc[r][1]);
            o.z = psum(acc[r][2]); o.w = psum(acc[r][3]);
            *reinterpret_cast<float4*>(g_T2 + ((size_t)b*NN + it0 + i0 + r)*DD + e0) = o;
        }
    } else if (bid < 272) {
        // ---- meanX for batch b; also zero fold counters ----
        __shared__ float red[256];
        const int b = bid - 256;
        if (tid < 8) g_cnt[b*8 + tid] = 0;
        const int d = tid & 63, g = tid >> 6;
        float xs = 0.f;
        for (int j = g; j < NN; j += 4) xs += X[((size_t)b*NN + j)*DD + d];
        red[tid] = xs; __syncthreads();
        if (g == 0)
            g_meanX[b*DD + d] = (red[d] + red[d+64] + red[d+128] + red[d+192]) * (1.f/NN);
    } else {
        // ---- per-row stats: rowmean, diag, r ----
        int gw = (bid - 272) * 8 + (tid >> 5);
        int lane = tid & 31;
        const float4* arow = reinterpret_cast<const float4*>(A) + (size_t)gw * (NN/4);
        float s = 0.f;
#pragma unroll
        for (int w = 0; w < 8; ++w) {
            float4 v = arow[lane + (w << 5)];
            s += (v.x + v.y) + (v.z + v.w);
        }
        const float* xrow = X + (size_t)gw * DD;
        float p = xrow[lane] * wA1[lane] + xrow[lane+32] * wA1[lane+32];
#pragma unroll
        for (int o = 16; o; o >>= 1) {
            s += __shfl_xor_sync(0xffffffffu, s, o);
            p += __shfl_xor_sync(0xffffffffu, p, o);
        }
        if (lane == 0) {
            int i = gw & (NN-1);
            float d = A[(size_t)gw*NN + i];
            float rm = s * (1.f/NN);
            g_rowmean[gw] = rm;
            g_diag[gw]    = d;
            g_r[gw]       = coeffs[3]*rm + coeffs[4]*d + p;
        }
    }
}

// ============ kernel 2: finish (batch scalars computed in-block) ==========
__global__ __launch_bounds__(256) void k_finish(
    const float* __restrict__ coeffs, const float* __restrict__ wA2,
    const float* __restrict__ w12, const float* __restrict__ w15, const float* __restrict__ w16,
    const float* __restrict__ w22, const float* __restrict__ w25, const float* __restrict__ w26,
    const float* __restrict__ w13, const float* __restrict__ w14,
    const float* __restrict__ w23, const float* __restrict__ w24,
    float* __restrict__ x1o)
{
    __shared__ __align__(16) float Xs[128*DD];
    __shared__ float red[256];
    __shared__ __align__(16) float pg1s[DD], pg2s[DD];
    __shared__ float s_mall, s_mdiag;
    const int b = blockIdx.y;
    const int it0 = blockIdx.x << 7;
    const int tid = threadIdx.x;

    float v1 = 0.f, v2 = 0.f;
    for (int i = tid; i < NN; i += 256) { v1 += g_rowmean[b*NN+i]; v2 += g_diag[b*NN+i]; }
    red[tid] = v1; __syncthreads();
    for (int o = 128; o > 0; o >>= 1) { if (tid < o) red[tid] += red[tid+o]; __syncthreads(); }
    if (tid == 0) s_mall = red[0]*(1.f/NN);
    __syncthreads();
    red[tid] = v2; __syncthreads();
    for (int o = 128; o > 0; o >>= 1) { if (tid < o) red[tid] += red[tid+o]; __syncthreads(); }
    if (tid == 0) s_mdiag = red[0]*(1.f/NN);
    __syncthreads();

    float mall = s_mall, mdiag = s_mdiag;
    if (tid == 0) {
        float p2 = 0.f;
        for (int k = 0; k < DD; ++k) p2 += g_meanX[b*DD+k]*wA2[k];
        g_s[b] = coeffs[1]*mall + coeffs[2]*mdiag + p2;
    } else if (tid >= 64 && tid < 128) {
        int e = tid - 64;
        float a = 0.f;
        for (int k = 0; k < DD; ++k) a += g_meanX[b*DD+k]*w12[e*DD+k];
        pg1s[e] = a + mdiag*w15[e] + mall*w16[e];
    } else if (tid >= 128 && tid < 192) {
        int e = tid - 128;
        float a = 0.f;
        for (int k = 0; k < DD; ++k) a += g_meanX[b*DD+k]*w22[e*DD+k];
        pg2s[e] = a + mdiag*w25[e] + mall*w26[e];
    }
    __syncthreads();

    const int tx = tid & 15, ty = tid >> 4;
    const int e0 = tx << 2, i0 = ty << 3;

    float4 wc1 = *reinterpret_cast<const float4*>(w13 + e0);
    float4 wd1 = *reinterpret_cast<const float4*>(w14 + e0);
    float4 pg1 = *reinterpret_cast<const float4*>(pg1s + e0);
    float4 wc2 = *reinterpret_cast<const float4*>(w23 + e0);
    float4 wd2 = *reinterpret_cast<const float4*>(w24 + e0);
    float4 pg2 = *reinterpret_cast<const float4*>(pg2s + e0);

#pragma unroll
    for (int r = 0; r < 8; ++r) {
        int gidx = b*NN + it0 + i0 + r;
        float rm = g_rowmean[gidx], dg = g_diag[gidx];
        size_t off = (size_t)gidx*DD + e0;
        float4 t1 = *reinterpret_cast<const float4*>(x1o + off);
        t1.x += rm*wc1.x + dg*wd1.x + pg1.x;
        t1.y += rm*wc1.y + dg*wd1.y + pg1.y;
        t1.z += rm*wc1.z + dg*wd1.z + pg1.z;
        t1.w += rm*wc1.w + dg*wd1.w + pg1.w;
        *reinterpret_cast<float4*>(x1o + off) = t1;
        float4 t2 = *reinterpret_cast<const float4*>(g_T2 + off);
        float4 o2;
        o2.x = t2.x + rm*wc2.x + dg*wd2.x + pg2.x;
        o2.y = t2.y + rm*wc2.y + dg*wd2.y + pg2.y;
        o2.z = t2.z + rm*wc2.z + dg*wd2.z + pg2.z;
        o2.w = t2.w + rm*wc2.w + dg*wd2.w + pg2.w;
        *reinterpret_cast<float4*>(Xs + (i0+r)*DD + e0) = o2;
    }
    __syncthreads();

    const int e = tid & 63, rc = tid >> 6;
#pragma unroll
    for (int rr = 0; rr < 8; ++rr) {
        int rowl = (rc << 5) + (rr << 2);
        float v0 = Xs[(rowl+0)*DD + e], v1 = Xs[(rowl+1)*DD + e];
        float v2 = Xs[(rowl+2)*DD + e], v3 = Xs[(rowl+3)*DD + e];
        uint32_t b0 = __float_as_uint(v0), b1 = __float_as_uint(v1);
        uint32_t b2 = __float_as_uint(v2), b3 = __float_as_uint(v3);
        float l0 = v0 - __uint_as_float(b0 & 0xffff0000u);
        float l1 = v1 - __uint_as_float(b1 & 0xffff0000u);
        float l2 = v2 - __uint_as_float(b2 & 0xffff0000u);
        float l3 = v3 - __uint_as_float(b3 & 0xffff0000u);
        uint2 hp, lp;
        hp.x = prmt7632(b0, b1); hp.y = prmt7632(b2, b3);
        lp.x = prmt7632(__float_as_uint(l0), __float_as_uint(l1));
        lp.y = prmt7632(__float_as_uint(l2), __float_as_uint(l3));
        size_t off = (((size_t)b*DD + e)*NN + it0 + rowl) >> 1;
        *reinterpret_cast<uint2*>(g_Bhi + off) = hp;
        *reinterpret_cast<uint2*>(g_Blo + off) = lp;
    }
}

// ============ kernel 3: bf16x3 HMMA GEMM (split-K=2) + in-kernel fold =====
#define STG_U (2*128*20 + 2*64*20)   // 7680 u32 per stage (30 KB)
__global__ __launch_bounds__(256, 2) void k_gemm(
    const float* __restrict__ A, const float* __restrict__ coeffs,
    float* __restrict__ At, float* __restrict__ x1o)
{
    extern __shared__ __align__(16) uint32_t smu[];
    const int tid = threadIdx.x;
    const int wid = tid >> 5, lane = tid & 31;
    const int b = blockIdx.y, it0 = blockIdx.x << 7;
    const int kv = blockIdx.z;
    const int kbase = kv << 9;

    const int rb = tid >> 3;
    const int ci = (tid & 7) << 2;
    const int eb = tid >> 2;
    const int uc = (tid & 3) << 2;

    const float c0 = coeffs[0];
    const float sbv = g_s[b];
    float rloc[4];
#pragma unroll
    for (int i = 0; i < 4; ++i) rloc[i] = sbv + g_r[b*NN + it0 + rb + (i << 5)];

    const float* Ab = A  + ((size_t)b*NN + it0)*NN;
    float*       Ob = At + ((size_t)b*NN + it0)*NN;
    const uint32_t* Bhg = g_Bhi + (size_t)b*DD*(NN/2);
    const uint32_t* Blg = g_Blo + (size_t)b*DD*(NN/2);
    float*       Pb = (kv == 0 ? g_part0 : g_part1) + ((size_t)b*NN + it0)*DD;

    float acc[2][4][4];
#pragma unroll
    for (int mt = 0; mt < 2; ++mt)
#pragma unroll
        for (int nt = 0; nt < 4; ++nt)
#pragma unroll
            for (int q = 0; q < 4; ++q) acc[mt][nt][q] = 0.f;

    float4 Ar[4], rjv;
    uint4 Bh4, Bl4;
    auto fetch = [&](int s) {
        const int k0 = kbase + (s << 5);
        rjv = *reinterpret_cast<const float4*>(g_r + b*NN + k0 + ci);
#pragma unroll
        for (int i = 0; i < 4; ++i)
            Ar[i] = *reinterpret_cast<const float4*>(Ab + (size_t)(rb + (i << 5))*NN + k0 + ci);
        const int k0u = k0 >> 1;
        Bh4 = *reinterpret_cast<const uint4*>(Bhg + (size_t)eb*(NN/2) + k0u + uc);
        Bl4 = *reinterpret_cast<const uint4*>(Blg + (size_t)eb*(NN/2) + k0u + uc);
    };
    auto fill = [&](int s, int buf) {
        const int k0 = kbase + (s << 5);
        uint32_t* Ahi = smu + buf * STG_U;
        uint32_t* Alo = Ahi + 128*20;
        uint32_t* Bhi = Alo + 128*20;
        uint32_t* Blo = Bhi + 64*20;
#pragma unroll
        for (int i = 0; i < 4; ++i) {
            int row = rb + (i << 5);
            float4 atv;
            atv.x = fmaf(c0, Ar[i].x, rloc[i] + rjv.x);
            atv.y = fmaf(c0, Ar[i].y, rloc[i] + rjv.y);
            atv.z = fmaf(c0, Ar[i].z, rloc[i] + rjv.z);
            atv.w = fmaf(c0, Ar[i].w, rloc[i] + rjv.w);
            *reinterpret_cast<float4*>(Ob + (size_t)row*NN + k0 + ci) = atv;   // A_t out
            uint32_t bx = __float_as_uint(atv.x), by = __float_as_uint(atv.y);
            uint32_t bz = __float_as_uint(atv.z), bw = __float_as_uint(atv.w);
            float lx = atv.x - __uint_as_float(bx & 0xffff0000u);
            float ly = atv.y - __uint_as_float(by & 0xffff0000u);
            float lz = atv.z - __uint_as_float(bz & 0xffff0000u);
            float lw = atv.w - __uint_as_float(bw & 0xffff0000u);
            uint2 hp, lp;
            hp.x = prmt7632(bx, by); hp.y = prmt7632(bz, bw);
            lp.x = prmt7632(__float_as_uint(lx), __float_as_uint(ly));
            lp.y = prmt7632(__float_as_uint(lz), __float_as_uint(lw));
            *reinterpret_cast<uint2*>(Ahi + row*20 + (ci >> 1)) = hp;
            *reinterpret_cast<uint2*>(Alo + row*20 + (ci >> 1)) = lp;
        }
        *reinterpret_cast<uint4*>(Bhi + eb*20 + uc) = Bh4;
        *reinterpret_cast<uint4*>(Blo + eb*20 + uc) = Bl4;
    };

    const int g = lane >> 2, t = lane & 3;
    const int m0 = (wid & 3) << 5;
    const int e0 = (wid >> 2) << 5;

    fetch(0);
    fill(0, 0);
    __syncthreads();

    for (int s = 0; s < 16; ++s) {
        if (s < 15) fetch(s + 1);
        const uint32_t* Ahi = smu + (s & 1) * STG_U;
        const uint32_t* Alo = Ahi + 128*20;
        const uint32_t* Bhi = Alo + 128*20;
        const uint32_t* Blo = Bhi + 64*20;
#pragma unroll
        for (int ks = 0; ks < 2; ++ks) {
            const int kk2 = ks << 3;
            uint32_t ah[2][4], al[2][4];
#pragma unroll
            for (int mt = 0; mt < 2; ++mt) {
                const int rowb = m0 + (mt << 4);
                ah[mt][0] = Ahi[(rowb+g  )*20 + kk2 + t];
                ah[mt][1] = Ahi[(rowb+g+8)*20 + kk2 + t];
                ah[mt][2] = Ahi[(rowb+g  )*20 + kk2 + 4 + t];
                ah[mt][3] = Ahi[(rowb+g+8)*20 + kk2 + 4 + t];
                al[mt][0] = Alo[(rowb+g  )*20 + kk2 + t];
                al[mt][1] = Alo[(rowb+g+8)*20 + kk2 + t];
                al[mt][2] = Alo[(rowb+g  )*20 + kk2 + 4 + t];
                al[mt][3] = Alo[(rowb+g+8)*20 + kk2 + 4 + t];
            }
            uint32_t bh[4][2], bl[4][2];
#pragma unroll
            for (int nt = 0; nt < 4; ++nt) {
                const int er = (e0 + (nt << 3) + g)*20 + kk2 + t;
                bh[nt][0] = Bhi[er]; bh[nt][1] = Bhi[er + 4];
                bl[nt][0] = Blo[er]; bl[nt][1] = Blo[er + 4];
            }
#pragma unroll
            for (int mt = 0; mt < 2; ++mt)
#pragma unroll
                for (int nt = 0; nt < 4; ++nt)
                    mma16(acc[mt][nt], ah[mt], bh[nt][0], bh[nt][1]);
#pragma unroll
            for (int mt = 0; mt < 2; ++mt)
#pragma unroll
                for (int nt = 0; nt < 4; ++nt)
                    mma16(acc[mt][nt], ah[mt], bl[nt][0], bl[nt][1]);
#pragma unroll
            for (int mt = 0; mt < 2; ++mt)
#pragma unroll
                for (int nt = 0; nt < 4; ++nt)
                    mma16(acc[mt][nt], al[mt], bh[nt][0], bh[nt][1]);
        }
        if (s < 15) {
            fill(s + 1, (s + 1) & 1);
            __syncthreads();
        }
    }

    // ---- epilogue: store partial; second-arriving block folds into x1o ----
#pragma unroll
    for (int mt = 0; mt < 2; ++mt) {
        const int row1 = m0 + (mt << 4) + g;
        const size_t b1 = (size_t)row1*DD;
        const size_t b2 = b1 + 8*DD;
#pragma unroll
        for (int nt = 0; nt < 4; ++nt) {
            const int col = e0 + (nt << 3) + (t << 1);
            float2 o1; o1.x = acc[mt][nt][0]; o1.y = acc[mt][nt][1];
            *reinterpret_cast<float2*>(Pb + b1 + col) = o1;
            float2 o2; o2.x = acc[mt][nt][2]; o2.y = acc[mt][nt][3];
            *reinterpret_cast<float2*>(Pb + b2 + col) = o2;
        }
    }
    __threadfence();
    __syncthreads();
    __shared__ int s_old;
    if (tid == 0) s_old = atomicAdd(&g_cnt[b*8 + blockIdx.x], 1);
    __syncthreads();
    if (s_old == 1) {
        const float inv = 1.0f / 1024.0f;
        const float* P0 = g_part0 + ((size_t)b*NN + it0)*DD;
        const float* P1 = g_part1 + ((size_t)b*NN + it0)*DD;
        float* Xo = x1o + ((size_t)b*NN + it0)*DD;
#pragma unroll
        for (int it = 0; it < 8; ++it) {
            int i = (it * 256 + tid) << 2;
            float4 p0 = *reinterpret_cast<const float4*>(P0 + i);
            float4 p1 = *reinterpret_cast<const float4*>(P1 + i);
            float4 x  = *reinterpret_cast<const float4*>(Xo + i);
            x.x += (p0.x + p1.x) * inv;
            x.y += (p0.y + p1.y) * inv;
            x.z += (p0.z + p1.z) * inv;
            x.w += (p0.w + p1.w) * inv;
            *reinterpret_cast<float4*>(Xo + i) = x;
        }
    }
}

// ---------------- launch ----------------
extern "C" void kernel_launch(void* const* d_in, const int* in_sizes, int n_in,
                              void* d_out, int out_size)
{
    const float* A      = (const float*)d_in[0];
    const float* X      = (const float*)d_in[1];
    const float* coeffs = (const float*)d_in[2];
    const float* wA1    = (const float*)d_in[3];
    const float* wA2    = (const float*)d_in[4];
    const float* w11    = (const float*)d_in[5];
    const float* w12    = (const float*)d_in[6];
    const float* w13    = (const float*)d_in[7];
    const float* w14    = (const float*)d_in[8];
    const float* w15    = (const float*)d_in[9];
    const float* w16    = (const float*)d_in[10];
    const float* w21    = (const float*)d_in[11];
    const float* w22    = (const float*)d_in[12];
    const float* w23    = (const float*)d_in[13];
    const float* w24    = (const float*)d_in[14];
    const float* w25    = (const float*)d_in[15];
    const float* w26    = (const float*)d_in[16];

    float* out = (float*)d_out;
    float* x1o = out + OUT_OFF;

    const int FRONT_SMEM = (64*DD + 2*64*68) * (int)sizeof(float);   // 51200
    cudaFuncSetAttribute(k_front, cudaFuncAttributeMaxDynamicSharedMemorySize, FRONT_SMEM);
    const int GEMM_SMEM = 2 * STG_U * (int)sizeof(uint32_t);         // 61440
    cudaFuncSetAttribute(k_gemm, cudaFuncAttributeMaxDynamicSharedMemorySize, GEMM_SMEM);

    k_front  <<<2320, 256, FRONT_SMEM>>>(A, X, coeffs, wA1, w11, w21, x1o);
    k_finish <<<dim3(8,16), 256>>>(coeffs, wA2, w12, w15, w16, w22, w25, w26,
                                   w13, w14, w23, w24, x1o);
    k_gemm   <<<dim3(8,16,2), 256, GEMM_SMEM>>>(A, coeffs, out, x1o);
}

// round 16
// speedup vs baseline: 1.0967x; 1.0967x over previous
#include <cuda_runtime.h>
#include <cuda_bf16.h>
#include <stdint.h>

#define NB 16
#define NN 1024
#define DD 64
#define OUT_OFF ((size_t)NB * NN * NN)

// ---------------- scratch (device globals; no allocation) ----------------
__device__ float g_rowmean[NB*NN];
__device__ float g_diag[NB*NN];
__device__ float g_r[NB*NN];            // c3*rowmean + c4*diag + p1
__device__ float g_s[NB];               // c1*mean_all + c2*mean_diag + p2
__device__ float g_meanX[NB*DD];
__device__ float g_T2[(size_t)NB*NN*DD];        // raw X@W2^T
__device__ uint32_t g_Bhi[(size_t)NB*DD*NN/2];  // bf16x2-packed hi of X2_t^T [b][e][k/2]
__device__ uint32_t g_Blo[(size_t)NB*DD*NN/2];  // bf16x2-packed lo residual
__device__ float g_part0[(size_t)NB*NN*DD];     // split-K partial (kv=0)
__device__ float g_part1[(size_t)NB*NN*DD];     // split-K partial (kv=1)
__device__ int   g_cnt[NB*8];                    // fold counters (zeroed by k_front)

// ---------------- packed fp32x2 helpers ----------------
__device__ __forceinline__ void fma2(unsigned long long &d,
                                     unsigned long long a,
                                     unsigned long long b) {
    asm("fma.rn.f32x2 %0, %1, %2, %0;" : "+l"(d) : "l"(a), "l"(b));
}
__device__ __forceinline__ float psum(unsigned long long v) {
    return __uint_as_float((unsigned)v) + __uint_as_float((unsigned)(v >> 32));
}

// ---------------- bf16 split helpers ----------------
__device__ __forceinline__ uint32_t prmt7632(uint32_t a, uint32_t b) {
    uint32_t d;
    asm("prmt.b32 %0, %1, %2, 0x7632;" : "=r"(d) : "r"(a), "r"(b));
    return d;
}

// ---------------- m16n8k16 bf16 mma (HMMA, baseline PTX) ----------------
__device__ __forceinline__ void mma16(float* c, const uint32_t* a,
                                      uint32_t b0, uint32_t b1) {
    asm("mma.sync.aligned.m16n8k16.row.col.f32.bf16.bf16.f32 "
        "{%0,%1,%2,%3}, {%4,%5,%6,%7}, {%8,%9}, {%0,%1,%2,%3};"
        : "+f"(c[0]), "+f"(c[1]), "+f"(c[2]), "+f"(c[3])
        : "r"(a[0]), "r"(a[1]), "r"(a[2]), "r"(a[3]), "r"(b0), "r"(b1));
}

// ============ kernel 1 (fused front) ============
// blocks 0-127  : X@W GEMMs, 128-row tiles (R14-proven)
// blocks 128-143: meanX + counter zero
// blocks 144-655: per-row stats, 4 rows/warp = 32 rows/block (wave-count cut 4x)
__global__ __launch_bounds__(256) void k_front(
    const float* __restrict__ A, const float* __restrict__ X,
    const float* __restrict__ coeffs, const float* __restrict__ wA1,
    const float* __restrict__ w11, const float* __restrict__ w21,
    float* __restrict__ x1o)
{
    const int bid = blockIdx.x;
    const int tid = threadIdx.x;

    if (bid < 128) {
        // ---- X@W1^T -> x1o (raw), X@W2^T -> g_T2 (raw); 128-row tile ----
        extern __shared__ __align__(16) float sm[];
        float* Xs = sm;               // [128][64]
        float* W1 = sm + 128*DD;      // [64][68]
        float* W2 = W1 + 64*68;       // [64][68]

        const int b = bid >> 3;
        const int it0 = (bid & 7) << 7;
        const int c4 = tid & 15, r0 = tid >> 4;
        const int ci = c4 << 2;

        const float* Xb = X + ((size_t)b*NN + it0)*DD;
#pragma unroll
        for (int t = 0; t < 8; ++t) {
            int row = r0 + (t << 4);
            *reinterpret_cast<float4*>(Xs + row*DD + ci) =
                *reinterpret_cast<const float4*>(Xb + (size_t)row*DD + ci);
        }
#pragma unroll
        for (int t = 0; t < 4; ++t) {
            int e = r0 + (t << 4);
            *reinterpret_cast<float4*>(W1 + e*68 + ci) = *reinterpret_cast<const float4*>(w11 + e*DD + ci);
            *reinterpret_cast<float4*>(W2 + e*68 + ci) = *reinterpret_cast<const float4*>(w21 + e*DD + ci);
        }
        __syncthreads();

        const int tx = tid & 15, ty = tid >> 4;
        const int e0 = tx << 2, i0 = ty << 3;

        unsigned long long acc[8][4];
#pragma unroll
        for (int r = 0; r < 8; ++r)
#pragma unroll
            for (int q = 0; q < 4; ++q) acc[r][q] = 0ull;
#pragma unroll 2
        for (int d = 0; d < DD; d += 4) {
            ulonglong2 a[8];
#pragma unroll
            for (int r = 0; r < 8; ++r)
                a[r] = *reinterpret_cast<const ulonglong2*>(Xs + (i0+r)*DD + d);
#pragma unroll
            for (int q = 0; q < 4; ++q) {
                ulonglong2 bv = *reinterpret_cast<const ulonglong2*>(W1 + (e0+q)*68 + d);
#pragma unroll
                for (int r = 0; r < 8; ++r) { fma2(acc[r][q], a[r].x, bv.x); fma2(acc[r][q], a[r].y, bv.y); }
            }
        }
#pragma unroll
        for (int r = 0; r < 8; ++r) {
            float4 o;
            o.x = psum(acc[r][0]); o.y = psum(acc[r][1]);
            o.z = psum(acc[r][2]); o.w = psum(acc[r][3]);
            *reinterpret_cast<float4*>(x1o + ((size_t)b*NN + it0 + i0 + r)*DD + e0) = o;
        }
#pragma unroll
        for (int r = 0; r < 8; ++r)
#pragma unroll
            for (int q = 0; q < 4; ++q) acc[r][q] = 0ull;
#pragma unroll 2
        for (int d = 0; d < DD; d += 4) {
            ulonglong2 a[8];
#pragma unroll
            for (int r = 0; r < 8; ++r)
                a[r] = *reinterpret_cast<const ulonglong2*>(Xs + (i0+r)*DD + d);
#pragma unroll
            for (int q = 0; q < 4; ++q) {
                ulonglong2 bv = *reinterpret_cast<const ulonglong2*>(W2 + (e0+q)*68 + d);
#pragma unroll
                for (int r = 0; r < 8; ++r) { fma2(acc[r][q], a[r].x, bv.x); fma2(acc[r][q], a[r].y, bv.y); }
            }
        }
#pragma unroll
        for (int r = 0; r < 8; ++r) {
            float4 o;
            o.x = psum(acc[r][0]); o.y = psum(acc[r][1]);
            o.z = psum(acc[r][2]); o.w = psum(acc[r][3]);
            *reinterpret_cast<float4*>(g_T2 + ((size_t)b*NN + it0 + i0 + r)*DD + e0) = o;
        }
    } else if (bid < 144) {
        // ---- meanX for batch b; also zero fold counters ----
        __shared__ float red[256];
        const int b = bid - 128;
        if (tid < 8) g_cnt[b*8 + tid] = 0;
        const int d = tid & 63, g = tid >> 6;
        float xs = 0.f;
        for (int j = g; j < NN; j += 4) xs += X[((size_t)b*NN + j)*DD + d];
        red[tid] = xs; __syncthreads();
        if (g == 0)
            g_meanX[b*DD + d] = (red[d] + red[d+64] + red[d+128] + red[d+192]) * (1.f/NN);
    } else {
        // ---- per-row stats: 4 rows per warp (interleaved loads for MLP) ----
        const int warp = tid >> 5, lane = tid & 31;
        const int gw0 = (bid - 144) * 32 + (warp << 2);   // 4 consecutive rows
        const float4* a0 = reinterpret_cast<const float4*>(A) + (size_t)(gw0+0) * (NN/4);
        const float4* a1 = reinterpret_cast<const float4*>(A) + (size_t)(gw0+1) * (NN/4);
        const float4* a2 = reinterpret_cast<const float4*>(A) + (size_t)(gw0+2) * (NN/4);
        const float4* a3 = reinterpret_cast<const float4*>(A) + (size_t)(gw0+3) * (NN/4);
        float s0 = 0.f, s1 = 0.f, s2 = 0.f, s3 = 0.f;
#pragma unroll
        for (int w = 0; w < 8; ++w) {
            int idx = lane + (w << 5);
            float4 v0 = a0[idx], v1 = a1[idx], v2 = a2[idx], v3 = a3[idx];
            s0 += (v0.x + v0.y) + (v0.z + v0.w);
            s1 += (v1.x + v1.y) + (v1.z + v1.w);
            s2 += (v2.x + v2.y) + (v2.z + v2.w);
            s3 += (v3.x + v3.y) + (v3.z + v3.w);
        }
        float wa = wA1[lane], wb = wA1[lane+32];
        float p0 = X[(size_t)(gw0+0)*DD + lane]*wa + X[(size_t)(gw0+0)*DD + lane+32]*wb;
        float p1 = X[(size_t)(gw0+1)*DD + lane]*wa + X[(size_t)(gw0+1)*DD + lane+32]*wb;
        float p2 = X[(size_t)(gw0+2)*DD + lane]*wa + X[(size_t)(gw0+2)*DD + lane+32]*wb;
        float p3 = X[(size_t)(gw0+3)*DD + lane]*wa + X[(size_t)(gw0+3)*DD + lane+32]*wb;
#pragma unroll
        for (int o = 16; o; o >>= 1) {
            s0 += __shfl_xor_sync(0xffffffffu, s0, o);
            s1 += __shfl_xor_sync(0xffffffffu, s1, o);
            s2 += __shfl_xor_sync(0xffffffffu, s2, o);
            s3 += __shfl_xor_sync(0xffffffffu, s3, o);
            p0 += __shfl_xor_sync(0xffffffffu, p0, o);
            p1 += __shfl_xor_sync(0xffffffffu, p1, o);
            p2 += __shfl_xor_sync(0xffffffffu, p2, o);
            p3 += __shfl_xor_sync(0xffffffffu, p3, o);
        }
        if (lane < 4) {
            int gw = gw0 + lane;
            float s = (lane == 0) ? s0 : (lane == 1) ? s1 : (lane == 2) ? s2 : s3;
            float p = (lane == 0) ? p0 : (lane == 1) ? p1 : (lane == 2) ? p2 : p3;
            int i = gw & (NN-1);
            float d = A[(size_t)gw*NN + i];
            float rm = s * (1.f/NN);
            g_rowmean[gw] = rm;
            g_diag[gw]    = d;
            g_r[gw]       = coeffs[3]*rm + coeffs[4]*d + p;
        }
    }
}

// ============ kernel 2: finish (batch scalars computed in-block) ==========
__global__ __launch_bounds__(256) void k_finish(
    const float* __restrict__ coeffs, const float* __restrict__ wA2,
    const float* __restrict__ w12, const float* __restrict__ w15, const float* __restrict__ w16,
    const float* __restrict__ w22, const float* __restrict__ w25, const float* __restrict__ w26,
    const float* __restrict__ w13, const float* __restrict__ w14,
    const float* __restrict__ w23, const float* __restrict__ w24,
    float* __restrict__ x1o)
{
    __shared__ __align__(16) float Xs[128*DD];
    __shared__ float red[256];
    __shared__ __align__(16) float pg1s[DD], pg2s[DD];
    __shared__ float s_mall, s_mdiag;
    const int b = blockIdx.y;
    const int it0 = blockIdx.x << 7;
    const int tid = threadIdx.x;

    float v1 = 0.f, v2 = 0.f;
    for (int i = tid; i < NN; i += 256) { v1 += g_rowmean[b*NN+i]; v2 += g_diag[b*NN+i]; }
    red[tid] = v1; __syncthreads();
    for (int o = 128; o > 0; o >>= 1) { if (tid < o) red[tid] += red[tid+o]; __syncthreads(); }
    if (tid == 0) s_mall = red[0]*(1.f/NN);
    __syncthreads();
    red[tid] = v2; __syncthreads();
    for (int o = 128; o > 0; o >>= 1) { if (tid < o) red[tid] += red[tid+o]; __syncthreads(); }
    if (tid == 0) s_mdiag = red[0]*(1.f/NN);
    __syncthreads();

    float mall = s_mall, mdiag = s_mdiag;
    if (tid == 0) {
        float p2 = 0.f;
        for (int k = 0; k < DD; ++k) p2 += g_meanX[b*DD+k]*wA2[k];
        g_s[b] = coeffs[1]*mall + coeffs[2]*mdiag + p2;
    } else if (tid >= 64 && tid < 128) {
        int e = tid - 64;
        float a = 0.f;
        for (int k = 0; k < DD; ++k) a += g_meanX[b*DD+k]*w12[e*DD+k];
        pg1s[e] = a + mdiag*w15[e] + mall*w16[e];
    } else if (tid >= 128 && tid < 192) {
        int e = tid - 128;
        float a = 0.f;
        for (int k = 0; k < DD; ++k) a += g_meanX[b*DD+k]*w22[e*DD+k];
        pg2s[e] = a + mdiag*w25[e] + mall*w26[e];
    }
    __syncthreads();

    const int tx = tid & 15, ty = tid >> 4;
    const int e0 = tx << 2, i0 = ty << 3;

    float4 wc1 = *reinterpret_cast<const float4*>(w13 + e0);
    float4 wd1 = *reinterpret_cast<const float4*>(w14 + e0);
    float4 pg1 = *reinterpret_cast<const float4*>(pg1s + e0);
    float4 wc2 = *reinterpret_cast<const float4*>(w23 + e0);
    float4 wd2 = *reinterpret_cast<const float4*>(w24 + e0);
    float4 pg2 = *reinterpret_cast<const float4*>(pg2s + e0);

#pragma unroll
    for (int r = 0; r < 8; ++r) {
        int gidx = b*NN + it0 + i0 + r;
        float rm = g_rowmean[gidx], dg = g_diag[gidx];
        size_t off = (size_t)gidx*DD + e0;
        float4 t1 = *reinterpret_cast<const float4*>(x1o + off);
        t1.x += rm*wc1.x + dg*wd1.x + pg1.x;
        t1.y += rm*wc1.y + dg*wd1.y + pg1.y;
        t1.z += rm*wc1.z + dg*wd1.z + pg1.z;
        t1.w += rm*wc1.w + dg*wd1.w + pg1.w;
        *reinterpret_cast<float4*>(x1o + off) = t1;
        float4 t2 = *reinterpret_cast<const float4*>(g_T2 + off);
        float4 o2;
        o2.x = t2.x + rm*wc2.x + dg*wd2.x + pg2.x;
        o2.y = t2.y + rm*wc2.y + dg*wd2.y + pg2.y;
        o2.z = t2.z + rm*wc2.z + dg*wd2.z + pg2.z;
        o2.w = t2.w + rm*wc2.w + dg*wd2.w + pg2.w;
        *reinterpret_cast<float4*>(Xs + (i0+r)*DD + e0) = o2;
    }
    __syncthreads();

    const int e = tid & 63, rc = tid >> 6;
#pragma unroll
    for (int rr = 0; rr < 8; ++rr) {
        int rowl = (rc << 5) + (rr << 2);
        float v0 = Xs[(rowl+0)*DD + e], v1 = Xs[(rowl+1)*DD + e];
        float v2 = Xs[(rowl+2)*DD + e], v3 = Xs[(rowl+3)*DD + e];
        uint32_t b0 = __float_as_uint(v0), b1 = __float_as_uint(v1);
        uint32_t b2 = __float_as_uint(v2), b3 = __float_as_uint(v3);
        float l0 = v0 - __uint_as_float(b0 & 0xffff0000u);
        float l1 = v1 - __uint_as_float(b1 & 0xffff0000u);
        float l2 = v2 - __uint_as_float(b2 & 0xffff0000u);
        float l3 = v3 - __uint_as_float(b3 & 0xffff0000u);
        uint2 hp, lp;
        hp.x = prmt7632(b0, b1); hp.y = prmt7632(b2, b3);
        lp.x = prmt7632(__float_as_uint(l0), __float_as_uint(l1));
        lp.y = prmt7632(__float_as_uint(l2), __float_as_uint(l3));
        size_t off = (((size_t)b*DD + e)*NN + it0 + rowl) >> 1;
        *reinterpret_cast<uint2*>(g_Bhi + off) = hp;
        *reinterpret_cast<uint2*>(g_Blo + off) = lp;
    }
}

// ============ kernel 3: bf16x3 HMMA GEMM (split-K=2) + in-kernel fold =====
#define STG_U (2*128*20 + 2*64*20)   // 7680 u32 per stage (30 KB)
__global__ __launch_bounds__(256, 2) void k_gemm(
    const float* __restrict__ A, const float* __restrict__ coeffs,
    float* __restrict__ At, float* __restrict__ x1o)
{
    extern __shared__ __align__(16) uint32_t smu[];
    const int tid = threadIdx.x;
    const int wid = tid >> 5, lane = tid & 31;
    const int b = blockIdx.y, it0 = blockIdx.x << 7;
    const int kv = blockIdx.z;
    const int kbase = kv << 9;

    const int rb = tid >> 3;
    const int ci = (tid & 7) << 2;
    const int eb = tid >> 2;
    const int uc = (tid & 3) << 2;

    const float c0 = coeffs[0];
    const float sbv = g_s[b];
    float rloc[4];
#pragma unroll
    for (int i = 0; i < 4; ++i) rloc[i] = sbv + g_r[b*NN + it0 + rb + (i << 5)];

    const float* Ab = A  + ((size_t)b*NN + it0)*NN;
    float*       Ob = At + ((size_t)b*NN + it0)*NN;
    const uint32_t* Bhg = g_Bhi + (size_t)b*DD*(NN/2);
    const uint32_t* Blg = g_Blo + (size_t)b*DD*(NN/2);
    float*       Pb = (kv == 0 ? g_part0 : g_part1) + ((size_t)b*NN + it0)*DD;

    float acc[2][4][4];
#pragma unroll
    for (int mt = 0; mt < 2; ++mt)
#pragma unroll
        for (int nt = 0; nt < 4; ++nt)
#pragma unroll
            for (int q = 0; q < 4; ++q) acc[mt][nt][q] = 0.f;

    float4 Ar[4], rjv;
    uint4 Bh4, Bl4;
    auto fetch = [&](int s) {
        const int k0 = kbase + (s << 5);
        rjv = *reinterpret_cast<const float4*>(g_r + b*NN + k0 + ci);
#pragma unroll
        for (int i = 0; i < 4; ++i)
            Ar[i] = *reinterpret_cast<const float4*>(Ab + (size_t)(rb + (i << 5))*NN + k0 + ci);
        const int k0u = k0 >> 1;
        Bh4 = *reinterpret_cast<const uint4*>(Bhg + (size_t)eb*(NN/2) + k0u + uc);
        Bl4 = *reinterpret_cast<const uint4*>(Blg + (size_t)eb*(NN/2) + k0u + uc);
    };
    auto fill = [&](int s, int buf) {
        const int k0 = kbase + (s << 5);
        uint32_t* Ahi = smu + buf * STG_U;
        uint32_t* Alo = Ahi + 128*20;
        uint32_t* Bhi = Alo + 128*20;
        uint32_t* Blo = Bhi + 64*20;
#pragma unroll
        for (int i = 0; i < 4; ++i) {
            int row = rb + (i << 5);
            float4 atv;
            atv.x = fmaf(c0, Ar[i].x, rloc[i] + rjv.x);
            atv.y = fmaf(c0, Ar[i].y, rloc[i] + rjv.y);
            atv.z = fmaf(c0, Ar[i].z, rloc[i] + rjv.z);
            atv.w = fmaf(c0, Ar[i].w, rloc[i] + rjv.w);
            *reinterpret_cast<float4*>(Ob + (size_t)row*NN + k0 + ci) = atv;   // A_t out
            uint32_t bx = __float_as_uint(atv.x), by = __float_as_uint(atv.y);
            uint32_t bz = __float_as_uint(atv.z), bw = __float_as_uint(atv.w);
            float lx = atv.x - __uint_as_float(bx & 0xffff0000u);
            float ly = atv.y - __uint_as_float(by & 0xffff0000u);
            float lz = atv.z - __uint_as_float(bz & 0xffff0000u);
            float lw = atv.w - __uint_as_float(bw & 0xffff0000u);
            uint2 hp, lp;
            hp.x = prmt7632(bx, by); hp.y = prmt7632(bz, bw);
            lp.x = prmt7632(__float_as_uint(lx), __float_as_uint(ly));
            lp.y = prmt7632(__float_as_uint(lz), __float_as_uint(lw));
            *reinterpret_cast<uint2*>(Ahi + row*20 + (ci >> 1)) = hp;
            *reinterpret_cast<uint2*>(Alo + row*20 + (ci >> 1)) = lp;
        }
        *reinterpret_cast<uint4*>(Bhi + eb*20 + uc) = Bh4;
        *reinterpret_cast<uint4*>(Blo + eb*20 + uc) = Bl4;
    };

    const int g = lane >> 2, t = lane & 3;
    const int m0 = (wid & 3) << 5;
    const int e0 = (wid >> 2) << 5;

    fetch(0);
    fill(0, 0);
    __syncthreads();

    for (int s = 0; s < 16; ++s) {
        if (s < 15) fetch(s + 1);
        const uint32_t* Ahi = smu + (s & 1) * STG_U;
        const uint32_t* Alo = Ahi + 128*20;
        const uint32_t* Bhi = Alo + 128*20;
        const uint32_t* Blo = Bhi + 64*20;
#pragma unroll
        for (int ks = 0; ks < 2; ++ks) {
            const int kk2 = ks << 3;
            uint32_t ah[2][4], al[2][4];
#pragma unroll
            for (int mt = 0; mt < 2; ++mt) {
                const int rowb = m0 + (mt << 4);
                ah[mt][0] = Ahi[(rowb+g  )*20 + kk2 + t];
                ah[mt][1] = Ahi[(rowb+g+8)*20 + kk2 + t];
                ah[mt][2] = Ahi[(rowb+g  )*20 + kk2 + 4 + t];
                ah[mt][3] = Ahi[(rowb+g+8)*20 + kk2 + 4 + t];
                al[mt][0] = Alo[(rowb+g  )*20 + kk2 + t];
                al[mt][1] = Alo[(rowb+g+8)*20 + kk2 + t];
                al[mt][2] = Alo[(rowb+g  )*20 + kk2 + 4 + t];
                al[mt][3] = Alo[(rowb+g+8)*20 + kk2 + 4 + t];
            }
            uint32_t bh[4][2], bl[4][2];
#pragma unroll
            for (int nt = 0; nt < 4; ++nt) {
                const int er = (e0 + (nt << 3) + g)*20 + kk2 + t;
                bh[nt][0] = Bhi[er]; bh[nt][1] = Bhi[er + 4];
                bl[nt][0] = Blo[er]; bl[nt][1] = Blo[er + 4];
            }
#pragma unroll
            for (int mt = 0; mt < 2; ++mt)
#pragma unroll
                for (int nt = 0; nt < 4; ++nt)
                    mma16(acc[mt][nt], ah[mt], bh[nt][0], bh[nt][1]);
#pragma unroll
            for (int mt = 0; mt < 2; ++mt)
#pragma unroll
                for (int nt = 0; nt < 4; ++nt)
                    mma16(acc[mt][nt], ah[mt], bl[nt][0], bl[nt][1]);
#pragma unroll
            for (int mt = 0; mt < 2; ++mt)
#pragma unroll
                for (int nt = 0; nt < 4; ++nt)
                    mma16(acc[mt][nt], al[mt], bh[nt][0], bh[nt][1]);
        }
        if (s < 15) {
            fill(s + 1, (s + 1) & 1);
            __syncthreads();
        }
    }

    // ---- epilogue: store partial; second-arriving block folds into x1o ----
#pragma unroll
    for (int mt = 0; mt < 2; ++mt) {
        const int row1 = m0 + (mt << 4) + g;
        const size_t b1 = (size_t)row1*DD;
        const size_t b2 = b1 + 8*DD;
#pragma unroll
        for (int nt = 0; nt < 4; ++nt) {
            const int col = e0 + (nt << 3) + (t << 1);
            float2 o1; o1.x = acc[mt][nt][0]; o1.y = acc[mt][nt][1];
            *reinterpret_cast<float2*>(Pb + b1 + col) = o1;
            float2 o2; o2.x = acc[mt][nt][2]; o2.y = acc[mt][nt][3];
            *reinterpret_cast<float2*>(Pb + b2 + col) = o2;
        }
    }
    __threadfence();
    __syncthreads();
    __shared__ int s_old;
    if (tid == 0) s_old = atomicAdd(&g_cnt[b*8 + blockIdx.x], 1);
    __syncthreads();
    if (s_old == 1) {
        const float inv = 1.0f / 1024.0f;
        const float* P0 = g_part0 + ((size_t)b*NN + it0)*DD;
        const float* P1 = g_part1 + ((size_t)b*NN + it0)*DD;
        float* Xo = x1o + ((size_t)b*NN + it0)*DD;
#pragma unroll
        for (int it = 0; it < 8; ++it) {
            int i = (it * 256 + tid) << 2;
            float4 p0 = *reinterpret_cast<const float4*>(P0 + i);
            float4 p1 = *reinterpret_cast<const float4*>(P1 + i);
            float4 x  = *reinterpret_cast<const float4*>(Xo + i);
            x.x += (p0.x + p1.x) * inv;
            x.y += (p0.y + p1.y) * inv;
            x.z += (p0.z + p1.z) * inv;
            x.w += (p0.w + p1.w) * inv;
            *reinterpret_cast<float4*>(Xo + i) = x;
        }
    }
}

// ---------------- launch ----------------
extern "C" void kernel_launch(void* const* d_in, const int* in_sizes, int n_in,
                              void* d_out, int out_size)
{
    const float* A      = (const float*)d_in[0];
    const float* X      = (const float*)d_in[1];
    const float* coeffs = (const float*)d_in[2];
    const float* wA1    = (const float*)d_in[3];
    const float* wA2    = (const float*)d_in[4];
    const float* w11    = (const float*)d_in[5];
    const float* w12    = (const float*)d_in[6];
    const float* w13    = (const float*)d_in[7];
    const float* w14    = (const float*)d_in[8];
    const float* w15    = (const float*)d_in[9];
    const float* w16    = (const float*)d_in[10];
    const float* w21    = (const float*)d_in[11];
    const float* w22    = (const float*)d_in[12];
    const float* w23    = (const float*)d_in[13];
    const float* w24    = (const float*)d_in[14];
    const float* w25    = (const float*)d_in[15];
    const float* w26    = (const float*)d_in[16];

    float* out = (float*)d_out;
    float* x1o = out + OUT_OFF;

    const int FRONT_SMEM = (128*DD + 2*64*68) * (int)sizeof(float);  // 67584
    cudaFuncSetAttribute(k_front, cudaFuncAttributeMaxDynamicSharedMemorySize, FRONT_SMEM);
    const int GEMM_SMEM = 2 * STG_U * (int)sizeof(uint32_t);         // 61440
    cudaFuncSetAttribute(k_gemm, cudaFuncAttributeMaxDynamicSharedMemorySize, GEMM_SMEM);

    k_front  <<<656, 256, FRONT_SMEM>>>(A, X, coeffs, wA1, w11, w21, x1o);
    k_finish <<<dim3(8,16), 256>>>(coeffs, wA2, w12, w15, w16, w22, w25, w26,
                                   w13, w14, w23, w24, x1o);
    k_gemm   <<<dim3(8,16,2), 256, GEMM_SMEM>>>(A, coeffs, out, x1o);
}